// round 1
// baseline (speedup 1.0000x reference)
#include <cuda_runtime.h>
#include <cstdint>

// Self_attention: out = softmax(QK^T/sqrt(S) + cauchy_bias, causal) @ V
// B=8, S=2048, D=512, fp32 in/out. Flash-attention, tf32 mma.sync.

#define B_   8
#define S_   2048
#define D_   512
#define BM   64      // query rows per CTA
#define BN   64      // kv rows per block
#define DC   128     // d-chunk width
#define QP   136     // smem pitch for Q/K/V chunk tiles (== 8 mod 32 -> conflict free)
#define PP   72      // smem pitch for P tile
#define OP   520     // smem pitch for O accumulator
#define NT   128     // threads (4 warps)

__device__ __forceinline__ uint32_t f2tf(float x) {
    uint32_t u;
    asm("cvt.rna.tf32.f32 %0, %1;" : "=r"(u) : "f"(x));
    return u;
}

__device__ __forceinline__ void mma8(float& c0, float& c1, float& c2, float& c3,
                                     uint32_t a0, uint32_t a1, uint32_t a2, uint32_t a3,
                                     uint32_t b0, uint32_t b1) {
    asm volatile(
        "mma.sync.aligned.m16n8k8.row.col.f32.tf32.tf32.f32 "
        "{%0,%1,%2,%3},{%4,%5,%6,%7},{%8,%9},{%0,%1,%2,%3};"
        : "+f"(c0), "+f"(c1), "+f"(c2), "+f"(c3)
        : "r"(a0), "r"(a1), "r"(a2), "r"(a3), "r"(b0), "r"(b1));
}

// Load a [64 x 128] fp32 tile (row stride D_) from global, convert to tf32,
// store into smem with pitch QP.
__device__ __forceinline__ void load_tile(float* dst, const float* src, int tid) {
#pragma unroll
    for (int it = 0; it < 16; ++it) {
        int idx = tid + it * NT;        // 0..2047
        int r   = idx >> 5;             // 32 float4 per row
        int c4  = (idx & 31) << 2;
        float4 v = *reinterpret_cast<const float4*>(src + (size_t)r * D_ + c4);
        float4 w;
        w.x = __uint_as_float(f2tf(v.x));
        w.y = __uint_as_float(f2tf(v.y));
        w.z = __uint_as_float(f2tf(v.z));
        w.w = __uint_as_float(f2tf(v.w));
        *reinterpret_cast<float4*>(dst + r * QP + c4) = w;
    }
}

__global__ void __launch_bounds__(NT, 1)
attn_tf32_kernel(const float* __restrict__ Q, const float* __restrict__ K,
                 const float* __restrict__ V, float* __restrict__ O) {
    extern __shared__ float sm[];
    float* Osm  = sm;                 // [BM][OP]
    float* bufA = sm + BM * OP;       // Q chunk / P tile
    float* bufB = bufA + BM * QP;     // K chunk / V chunk / row sums

    const int tid  = threadIdx.x;
    const int lane = tid & 31;
    const int warp = tid >> 5;
    const int g    = lane >> 2;       // 0..7
    const int tg   = lane & 3;        // 0..3
    const int rb   = warp * 16;       // warp's row base within the tile

    const int qb = (S_ / BM - 1) - (int)blockIdx.x;  // heavy blocks first
    const int b  = blockIdx.y;

    const float* Qg = Q + ((size_t)b * S_ + (size_t)qb * BM) * D_;
    const float* Kg = K + (size_t)b * S_ * D_;
    const float* Vg = V + (size_t)b * S_ * D_;
    float*       Og = O + ((size_t)b * S_ + (size_t)qb * BM) * D_;

    // zero O accumulator
    for (int i = tid; i < BM * OP; i += NT) Osm[i] = 0.f;

    float m0 = -1e30f, m1 = -1e30f, l0 = 0.f, l1 = 0.f;
    const float scale = 0.0220970869120796f;  // 1/sqrt(2048)

    const int i0 = qb * BM + rb + g;   // global query row for fragment rows {c0,c1}
    const int i1 = i0 + 8;             // and {c2,c3}

    for (int kvb = 0; kvb <= qb; ++kvb) {
        // ---------- phase 1: S = Q K^T (accumulate over 4 d-chunks) ----------
        float c[8][4];
#pragma unroll
        for (int nt = 0; nt < 8; ++nt) {
            c[nt][0] = 0.f; c[nt][1] = 0.f; c[nt][2] = 0.f; c[nt][3] = 0.f;
        }
        for (int dc = 0; dc < 4; ++dc) {
            __syncthreads();  // everyone done with bufA/bufB previous use
            load_tile(bufA, Qg + dc * DC, tid);
            load_tile(bufB, Kg + (size_t)kvb * BN * D_ + dc * DC, tid);
            __syncthreads();
#pragma unroll
            for (int kk = 0; kk < 16; ++kk) {
                const float* qr = bufA + (rb + g) * QP + kk * 8 + tg;
                uint32_t a0 = __float_as_uint(qr[0]);
                uint32_t a1 = __float_as_uint(qr[8 * QP]);
                uint32_t a2 = __float_as_uint(qr[4]);
                uint32_t a3 = __float_as_uint(qr[8 * QP + 4]);
#pragma unroll
                for (int nt = 0; nt < 8; ++nt) {
                    const float* kr = bufB + (nt * 8 + g) * QP + kk * 8 + tg;
                    uint32_t b0 = __float_as_uint(kr[0]);
                    uint32_t b1 = __float_as_uint(kr[4]);
                    mma8(c[nt][0], c[nt][1], c[nt][2], c[nt][3], a0, a1, a2, a3, b0, b1);
                }
            }
        }

        // ---------- phase 2: scale + cauchy bias + causal mask + online softmax ----------
        const int jb = kvb * BN;
        float mx0 = -1e30f, mx1 = -1e30f;
#pragma unroll
        for (int nt = 0; nt < 8; ++nt) {
#pragma unroll
            for (int kq = 0; kq < 4; ++kq) {
                int i = (kq < 2) ? i0 : i1;
                int j = jb + nt * 8 + 2 * tg + (kq & 1);
                float s;
                if (j > i) {
                    s = -1e30f;
                } else {
                    float d = (float)(i - j);
                    s = c[nt][kq] * scale + 1.f / (1.f + 0.2f * d * d);
                }
                c[nt][kq] = s;
                if (kq < 2) mx0 = fmaxf(mx0, s); else mx1 = fmaxf(mx1, s);
            }
        }
        mx0 = fmaxf(mx0, __shfl_xor_sync(0xffffffffu, mx0, 1));
        mx0 = fmaxf(mx0, __shfl_xor_sync(0xffffffffu, mx0, 2));
        mx1 = fmaxf(mx1, __shfl_xor_sync(0xffffffffu, mx1, 1));
        mx1 = fmaxf(mx1, __shfl_xor_sync(0xffffffffu, mx1, 2));
        float mn0 = fmaxf(m0, mx0), mn1 = fmaxf(m1, mx1);
        float al0 = __expf(m0 - mn0), al1 = __expf(m1 - mn1);
        m0 = mn0; m1 = mn1;
        float su0 = 0.f, su1 = 0.f;
#pragma unroll
        for (int nt = 0; nt < 8; ++nt) {
            float p0 = __expf(c[nt][0] - mn0);
            float p1 = __expf(c[nt][1] - mn0);
            float p2 = __expf(c[nt][2] - mn1);
            float p3 = __expf(c[nt][3] - mn1);
            su0 += p0 + p1; su1 += p2 + p3;
            c[nt][0] = p0; c[nt][1] = p1; c[nt][2] = p2; c[nt][3] = p3;
        }
        su0 += __shfl_xor_sync(0xffffffffu, su0, 1);
        su0 += __shfl_xor_sync(0xffffffffu, su0, 2);
        su1 += __shfl_xor_sync(0xffffffffu, su1, 1);
        su1 += __shfl_xor_sync(0xffffffffu, su1, 2);
        l0 = l0 * al0 + su0;
        l1 = l1 * al1 + su1;

        // ---------- phase 3: P -> smem (aliases bufA; all warps must be past QK) ----------
        __syncthreads();
        float* Ps = bufA;
#pragma unroll
        for (int nt = 0; nt < 8; ++nt) {
            float2 pa, pb;
            pa.x = __uint_as_float(f2tf(c[nt][0]));
            pa.y = __uint_as_float(f2tf(c[nt][1]));
            pb.x = __uint_as_float(f2tf(c[nt][2]));
            pb.y = __uint_as_float(f2tf(c[nt][3]));
            *reinterpret_cast<float2*>(Ps + (rb + g) * PP + nt * 8 + 2 * tg) = pa;
            *reinterpret_cast<float2*>(Ps + (rb + g + 8) * PP + nt * 8 + 2 * tg) = pb;
        }
        // each warp only reads its OWN rows of Ps -> no extra sync needed here

        // ---------- phase 4: O = O*alpha + P V, per 128-wide d-chunk ----------
        for (int dc = 0; dc < 4; ++dc) {
            __syncthreads();  // all warps done reading bufB (K / previous V chunk)
            load_tile(bufB, Vg + (size_t)kvb * BN * D_ + dc * DC, tid);
            __syncthreads();
            float o[16][4];
#pragma unroll
            for (int nt = 0; nt < 16; ++nt) {
                o[nt][0] = 0.f; o[nt][1] = 0.f; o[nt][2] = 0.f; o[nt][3] = 0.f;
            }
#pragma unroll
            for (int kk = 0; kk < 8; ++kk) {
                const float* pr = Ps + (rb + g) * PP + kk * 8 + tg;
                uint32_t a0 = __float_as_uint(pr[0]);
                uint32_t a1 = __float_as_uint(pr[8 * PP]);
                uint32_t a2 = __float_as_uint(pr[4]);
                uint32_t a3 = __float_as_uint(pr[8 * PP + 4]);
#pragma unroll
                for (int nt = 0; nt < 16; ++nt) {
                    const float* vr = bufB + (kk * 8 + tg) * QP + nt * 8 + g;
                    uint32_t b0 = __float_as_uint(vr[0]);
                    uint32_t b1 = __float_as_uint(vr[4 * QP]);
                    mma8(o[nt][0], o[nt][1], o[nt][2], o[nt][3], a0, a1, a2, a3, b0, b1);
                }
            }
            // merge into O smem with this iteration's alpha
#pragma unroll
            for (int nt = 0; nt < 16; ++nt) {
                float* op0 = Osm + (rb + g) * OP + dc * DC + nt * 8 + 2 * tg;
                float2 v0 = *reinterpret_cast<float2*>(op0);
                v0.x = v0.x * al0 + o[nt][0];
                v0.y = v0.y * al0 + o[nt][1];
                *reinterpret_cast<float2*>(op0) = v0;
                float* op1 = Osm + (rb + g + 8) * OP + dc * DC + nt * 8 + 2 * tg;
                float2 v1 = *reinterpret_cast<float2*>(op1);
                v1.x = v1.x * al1 + o[nt][2];
                v1.y = v1.y * al1 + o[nt][3];
                *reinterpret_cast<float2*>(op1) = v1;
            }
        }
    }

    // ---------- epilogue: out = O / l ----------
    __syncthreads();
    float* Lr = bufB;  // bufB free now
    if (tg == 0) {
        Lr[rb + g]     = l0;
        Lr[rb + g + 8] = l1;
    }
    __syncthreads();
#pragma unroll 4
    for (int it = 0; it < 64; ++it) {
        int idx = tid + it * NT;        // 0..8191 (64 rows * 128 float4)
        int r   = idx >> 7;
        int c4  = (idx & 127) << 2;
        float inv = 1.0f / Lr[r];
        const float* os = Osm + r * OP + c4;
        float4 w = make_float4(os[0] * inv, os[1] * inv, os[2] * inv, os[3] * inv);
        *reinterpret_cast<float4*>(Og + (size_t)r * D_ + c4) = w;
    }
}

extern "C" void kernel_launch(void* const* d_in, const int* in_sizes, int n_in,
                              void* d_out, int out_size) {
    (void)in_sizes; (void)n_in; (void)out_size;
    const float* Q = (const float*)d_in[0];
    const float* K = (const float*)d_in[1];
    const float* V = (const float*)d_in[2];
    float* O = (float*)d_out;

    const size_t smem = (size_t)(BM * OP + 2 * BM * QP) * sizeof(float);  // 202752 B
    cudaFuncSetAttribute(attn_tf32_kernel,
                         cudaFuncAttributeMaxDynamicSharedMemorySize, (int)smem);

    dim3 grid(S_ / BM, B_);
    attn_tf32_kernel<<<grid, NT, smem>>>(Q, K, V, O);
}

// round 2
// speedup vs baseline: 2.1249x; 2.1249x over previous
#include <cuda_runtime.h>
#include <cstdint>

// Self_attention: out = softmax(QK^T/sqrt(S) + cauchy_bias, causal) @ V
// B=8, S=2048, D=512, fp32. Flash-attention, tf32 mma.sync, cp.async pipeline.

#define B_   8
#define S_   2048
#define D_   512
#define BM   64      // query rows per CTA
#define BN   64      // kv rows per block
#define DC   64      // d-chunk width
#define NDC  8       // D_/DC
#define QP   68      // pitch for Q/K chunk (==4 mod 32 -> conflict-free QK frag reads)
#define VP   72      // pitch for V chunk   (==8 mod 32 -> conflict-free PV frag reads)
#define PP   68      // pitch for P tile    (==4 mod 32)
#define OP   520     // pitch for O accumulator (==8 mod 32)
#define NT   256     // threads (8 warps)

#define CP_COMMIT() asm volatile("cp.async.commit_group;\n" ::: "memory")
#define CP_WAIT(n)  asm volatile("cp.async.wait_group %0;\n" :: "n"(n) : "memory")

__device__ __forceinline__ uint32_t f2tf(float x) {
    uint32_t u;
    asm("cvt.rna.tf32.f32 %0, %1;" : "=r"(u) : "f"(x));
    return u;
}

__device__ __forceinline__ void mma8(float& c0, float& c1, float& c2, float& c3,
                                     uint32_t a0, uint32_t a1, uint32_t a2, uint32_t a3,
                                     uint32_t b0, uint32_t b1) {
    asm volatile(
        "mma.sync.aligned.m16n8k8.row.col.f32.tf32.tf32.f32 "
        "{%0,%1,%2,%3},{%4,%5,%6,%7},{%8,%9},{%0,%1,%2,%3};"
        : "+f"(c0), "+f"(c1), "+f"(c2), "+f"(c3)
        : "r"(a0), "r"(a1), "r"(a2), "r"(a3), "r"(b0), "r"(b1));
}

// Issue async copy of a [64 x 64] fp32 tile (global row stride D_) into smem (pitch).
__device__ __forceinline__ void cp_chunk(float* dst, int pitch, const float* src, int tid) {
#pragma unroll
    for (int it = 0; it < 4; ++it) {
        int idx = tid + it * NT;          // 0..1023 (64 rows x 16 float4)
        int r   = idx >> 4;
        int c4  = (idx & 15) << 2;
        uint32_t da = (uint32_t)__cvta_generic_to_shared(dst + r * pitch + c4);
        asm volatile("cp.async.cg.shared.global [%0], [%1], 16;\n"
                     :: "r"(da), "l"(src + (size_t)r * D_ + c4) : "memory");
    }
}

__global__ void __launch_bounds__(NT, 1)
attn_tf32_kernel(const float* __restrict__ Q, const float* __restrict__ K,
                 const float* __restrict__ V, float* __restrict__ O) {
    extern __shared__ float sm[];
    float* Osm = sm;                      // [64][520]
    float* PB  = Osm + BM * OP;           // [64][68]  P tile (stored tf32-formatted)
    float* SB  = PB + BM * PP;            // 256 floats: stats exchange / row sums
    float* buf = SB + 256;                // 4 buffers of [64][72] (Q0,Q1,K0,K1 / V ring)
    const int BSZ = BM * VP;

    const int tid  = threadIdx.x;
    const int lane = tid & 31;
    const int warp = tid >> 5;
    const int g    = lane >> 2;           // 0..7
    const int tg   = lane & 3;            // 0..3
    const int wr   = warp & 3;            // row group
    const int wc   = warp >> 2;           // column half
    const int rb   = wr * 16;

    const int bid = blockIdx.x;
    const int b   = bid & 7;
    const int qb  = (S_ / BM - 1) - (bid >> 3);   // heavy blocks in wave 1

    const float* Qg = Q + ((size_t)b * S_ + (size_t)qb * BM) * D_;
    const float* Kg = K + (size_t)b * S_ * D_;
    const float* Vg = V + (size_t)b * S_ * D_;
    float*       Og = O + ((size_t)b * S_ + (size_t)qb * BM) * D_;

    float m0 = -1e30f, m1 = -1e30f, l0 = 0.f, l1 = 0.f;
    const float scale = 0.0220970869120796f;  // 1/sqrt(2048)
    const int i0 = qb * BM + rb + g;
    const int i1 = i0 + 8;

    for (int kvb = 0; kvb <= qb; ++kvb) {
        const float* Kb = Kg + (size_t)kvb * BN * D_;
        const float* Vb = Vg + (size_t)kvb * BN * D_;

        __syncthreads();   // all warps done reading V buffers of previous block

        // ---- phase 1: S = Q K^T, pipelined over 8 d-chunks ----
        cp_chunk(buf + 0 * BSZ, QP, Qg, tid);
        cp_chunk(buf + 2 * BSZ, QP, Kb, tid);
        CP_COMMIT();

        float c[4][4];
#pragma unroll
        for (int nt = 0; nt < 4; ++nt) {
            c[nt][0] = 0.f; c[nt][1] = 0.f; c[nt][2] = 0.f; c[nt][3] = 0.f;
        }

        for (int dc = 0; dc < NDC; ++dc) {
            CP_WAIT(0);
            __syncthreads();
            if (dc + 1 < NDC) {
                cp_chunk(buf + ((dc + 1) & 1) * BSZ,       QP, Qg + (dc + 1) * DC, tid);
                cp_chunk(buf + (2 + ((dc + 1) & 1)) * BSZ, QP, Kb + (dc + 1) * DC, tid);
                CP_COMMIT();
            }
            const float* Qs = buf + (dc & 1) * BSZ;
            const float* Ks = buf + (2 + (dc & 1)) * BSZ;
#pragma unroll
            for (int kk = 0; kk < 8; ++kk) {
                const float* qr = Qs + (rb + g) * QP + kk * 8 + tg;
                uint32_t a0 = f2tf(qr[0]);
                uint32_t a1 = f2tf(qr[8 * QP]);
                uint32_t a2 = f2tf(qr[4]);
                uint32_t a3 = f2tf(qr[8 * QP + 4]);
#pragma unroll
                for (int nt = 0; nt < 4; ++nt) {
                    const float* kr = Ks + (wc * 32 + nt * 8 + g) * QP + kk * 8 + tg;
                    uint32_t b0 = f2tf(kr[0]);
                    uint32_t b1 = f2tf(kr[4]);
                    mma8(c[nt][0], c[nt][1], c[nt][2], c[nt][3], a0, a1, a2, a3, b0, b1);
                }
            }
        }

        // ---- phase 2: bias + mask + online softmax (cross-warp stat exchange) ----
        const int jb = kvb * BN + wc * 32;
        float mx0 = -1e30f, mx1 = -1e30f;
#pragma unroll
        for (int nt = 0; nt < 4; ++nt) {
#pragma unroll
            for (int kq = 0; kq < 4; ++kq) {
                int i = (kq < 2) ? i0 : i1;
                int j = jb + nt * 8 + 2 * tg + (kq & 1);
                float s;
                if (j > i) {
                    s = -1e30f;
                } else {
                    float d = (float)(i - j);
                    s = c[nt][kq] * scale + 1.f / (1.f + 0.2f * d * d);
                }
                c[nt][kq] = s;
                if (kq < 2) mx0 = fmaxf(mx0, s); else mx1 = fmaxf(mx1, s);
            }
        }
        mx0 = fmaxf(mx0, __shfl_xor_sync(0xffffffffu, mx0, 1));
        mx0 = fmaxf(mx0, __shfl_xor_sync(0xffffffffu, mx0, 2));
        mx1 = fmaxf(mx1, __shfl_xor_sync(0xffffffffu, mx1, 1));
        mx1 = fmaxf(mx1, __shfl_xor_sync(0xffffffffu, mx1, 2));
        if (tg == 0) {
            SB[wc * 64 + rb + g]     = mx0;
            SB[wc * 64 + rb + g + 8] = mx1;
        }
        __syncthreads();
        mx0 = fmaxf(mx0, SB[(1 - wc) * 64 + rb + g]);
        mx1 = fmaxf(mx1, SB[(1 - wc) * 64 + rb + g + 8]);

        float mn0 = fmaxf(m0, mx0), mn1 = fmaxf(m1, mx1);
        float al0 = __expf(m0 - mn0), al1 = __expf(m1 - mn1);
        m0 = mn0; m1 = mn1;

        float su0 = 0.f, su1 = 0.f;
#pragma unroll
        for (int nt = 0; nt < 4; ++nt) {
            float p0 = __expf(c[nt][0] - mn0);
            float p1 = __expf(c[nt][1] - mn0);
            float p2 = __expf(c[nt][2] - mn1);
            float p3 = __expf(c[nt][3] - mn1);
            su0 += p0 + p1; su1 += p2 + p3;
            c[nt][0] = p0; c[nt][1] = p1; c[nt][2] = p2; c[nt][3] = p3;
        }
        su0 += __shfl_xor_sync(0xffffffffu, su0, 1);
        su0 += __shfl_xor_sync(0xffffffffu, su0, 2);
        su1 += __shfl_xor_sync(0xffffffffu, su1, 1);
        su1 += __shfl_xor_sync(0xffffffffu, su1, 2);
        if (tg == 0) {
            SB[128 + wc * 64 + rb + g]     = su0;
            SB[128 + wc * 64 + rb + g + 8] = su1;
        }
        __syncthreads();
        su0 += SB[128 + (1 - wc) * 64 + rb + g];
        su1 += SB[128 + (1 - wc) * 64 + rb + g + 8];
        l0 = l0 * al0 + su0;
        l1 = l1 * al1 + su1;

        // ---- phase 3: P -> smem (tf32-formatted) ----
#pragma unroll
        for (int nt = 0; nt < 4; ++nt) {
            float2 pa, pb2;
            pa.x  = __uint_as_float(f2tf(c[nt][0]));
            pa.y  = __uint_as_float(f2tf(c[nt][1]));
            pb2.x = __uint_as_float(f2tf(c[nt][2]));
            pb2.y = __uint_as_float(f2tf(c[nt][3]));
            int colb = wc * 32 + nt * 8 + 2 * tg;
            *reinterpret_cast<float2*>(PB + (rb + g) * PP + colb)     = pa;
            *reinterpret_cast<float2*>(PB + (rb + g + 8) * PP + colb) = pb2;
        }

        // ---- phase 4: O = O*alpha + P V, 2-deep V pipeline over 8 d-chunks ----
        cp_chunk(buf + 0 * BSZ, VP, Vb, tid);      CP_COMMIT();
        cp_chunk(buf + 1 * BSZ, VP, Vb + DC, tid); CP_COMMIT();

        for (int dc = 0; dc < NDC; ++dc) {
            if (dc == NDC - 1) { CP_WAIT(0); } else { CP_WAIT(1); }
            __syncthreads();
            if (dc + 2 < NDC) {
                cp_chunk(buf + ((dc + 2) & 3) * BSZ, VP, Vb + (dc + 2) * DC, tid);
                CP_COMMIT();
            }
            const float* Vs = buf + (dc & 3) * BSZ;

            float o[4][4];
#pragma unroll
            for (int nt = 0; nt < 4; ++nt) {
                o[nt][0] = 0.f; o[nt][1] = 0.f; o[nt][2] = 0.f; o[nt][3] = 0.f;
            }
#pragma unroll
            for (int kk = 0; kk < 8; ++kk) {
                const float* pr = PB + (rb + g) * PP + kk * 8 + tg;
                uint32_t a0 = __float_as_uint(pr[0]);
                uint32_t a1 = __float_as_uint(pr[8 * PP]);
                uint32_t a2 = __float_as_uint(pr[4]);
                uint32_t a3 = __float_as_uint(pr[8 * PP + 4]);
#pragma unroll
                for (int nt = 0; nt < 4; ++nt) {
                    const float* vr = Vs + (kk * 8 + tg) * VP + (wc * 4 + nt) * 8 + g;
                    uint32_t b0 = f2tf(vr[0]);
                    uint32_t b1 = f2tf(vr[4 * VP]);
                    mma8(o[nt][0], o[nt][1], o[nt][2], o[nt][3], a0, a1, a2, a3, b0, b1);
                }
            }
#pragma unroll
            for (int nt = 0; nt < 4; ++nt) {
                float* op0 = Osm + (rb + g) * OP + dc * DC + (wc * 4 + nt) * 8 + 2 * tg;
                float* op1 = Osm + (rb + g + 8) * OP + dc * DC + (wc * 4 + nt) * 8 + 2 * tg;
                if (kvb == 0) {
                    *reinterpret_cast<float2*>(op0) = make_float2(o[nt][0], o[nt][1]);
                    *reinterpret_cast<float2*>(op1) = make_float2(o[nt][2], o[nt][3]);
                } else {
                    float2 v0 = *reinterpret_cast<float2*>(op0);
                    v0.x = v0.x * al0 + o[nt][0];
                    v0.y = v0.y * al0 + o[nt][1];
                    *reinterpret_cast<float2*>(op0) = v0;
                    float2 v1 = *reinterpret_cast<float2*>(op1);
                    v1.x = v1.x * al1 + o[nt][2];
                    v1.y = v1.y * al1 + o[nt][3];
                    *reinterpret_cast<float2*>(op1) = v1;
                }
            }
        }
    }

    // ---- epilogue: out = O / l ----
    __syncthreads();
    if (wc == 0 && tg == 0) {
        SB[rb + g]     = l0;
        SB[rb + g + 8] = l1;
    }
    __syncthreads();
#pragma unroll 4
    for (int it = 0; it < 32; ++it) {
        int idx = tid + it * NT;          // 64 rows x 128 float4
        int r   = idx >> 7;
        int c4  = (idx & 127) << 2;
        float inv = 1.0f / SB[r];
        const float* os = Osm + r * OP + c4;
        float4 w = make_float4(os[0] * inv, os[1] * inv, os[2] * inv, os[3] * inv);
        *reinterpret_cast<float4*>(Og + (size_t)r * D_ + c4) = w;
    }
}

extern "C" void kernel_launch(void* const* d_in, const int* in_sizes, int n_in,
                              void* d_out, int out_size) {
    (void)in_sizes; (void)n_in; (void)out_size;
    const float* Q = (const float*)d_in[0];
    const float* K = (const float*)d_in[1];
    const float* V = (const float*)d_in[2];
    float* O = (float*)d_out;

    const size_t smem = (size_t)(BM * OP + BM * PP + 256 + 4 * BM * VP) * sizeof(float); // 225280
    cudaFuncSetAttribute(attn_tf32_kernel,
                         cudaFuncAttributeMaxDynamicSharedMemorySize, (int)smem);

    attn_tf32_kernel<<<S_ / BM * B_, NT, smem>>>(Q, K, V, O);
}

// round 3
// speedup vs baseline: 2.2891x; 1.0773x over previous
#include <cuda_runtime.h>
#include <cstdint>

// Self_attention: out = softmax(QK^T/sqrt(S) + cauchy_bias, causal) @ V
// B=8, S=2048, D=512, fp32. Flash-attention, tf32 mma.sync, O in registers,
// 512 threads, V tile fully staged in smem per KV block.

#define B_   8
#define S_   2048
#define D_   512
#define BM   64      // query rows per CTA
#define BN   64      // kv rows per block
#define DC   64      // d-chunk width for Q/K/V streaming
#define NDC  8       // D_/DC
#define QP   68      // pitch Q/K chunk  (==4 mod 32)
#define PP   68      // pitch P tile     (==4 mod 32)
#define VPW  520     // pitch V full tile(==8 mod 32)
#define NT   512     // threads (16 warps)

#define CP_COMMIT() asm volatile("cp.async.commit_group;\n" ::: "memory")
#define CP_WAIT(n)  asm volatile("cp.async.wait_group %0;\n" :: "n"(n) : "memory")

__device__ __forceinline__ uint32_t f2tf(float x) {
    uint32_t u;
    asm("cvt.rna.tf32.f32 %0, %1;" : "=r"(u) : "f"(x));
    return u;
}

__device__ __forceinline__ void mma8(float& c0, float& c1, float& c2, float& c3,
                                     uint32_t a0, uint32_t a1, uint32_t a2, uint32_t a3,
                                     uint32_t b0, uint32_t b1) {
    asm volatile(
        "mma.sync.aligned.m16n8k8.row.col.f32.tf32.tf32.f32 "
        "{%0,%1,%2,%3},{%4,%5,%6,%7},{%8,%9},{%0,%1,%2,%3};"
        : "+f"(c0), "+f"(c1), "+f"(c2), "+f"(c3)
        : "r"(a0), "r"(a1), "r"(a2), "r"(a3), "r"(b0), "r"(b1));
}

// Async copy of a [64 x 64] fp32 tile (global row stride D_) into smem (pitch).
__device__ __forceinline__ void cp64(float* dst, int pitch, const float* src, int tid) {
#pragma unroll
    for (int it = 0; it < 2; ++it) {
        int idx = tid + it * NT;          // 0..1023 (64 rows x 16 float4)
        int r   = idx >> 4;
        int c4  = (idx & 15) << 2;
        uint32_t da = (uint32_t)__cvta_generic_to_shared(dst + r * pitch + c4);
        asm volatile("cp.async.cg.shared.global [%0], [%1], 16;\n"
                     :: "r"(da), "l"(src + (size_t)r * D_ + c4) : "memory");
    }
}

__global__ void __launch_bounds__(NT, 1)
attn_tf32_kernel(const float* __restrict__ Q, const float* __restrict__ K,
                 const float* __restrict__ V, float* __restrict__ Oout) {
    extern __shared__ float sm[];
    float* Vsm = sm;                       // [64][520]
    float* Qb  = Vsm + BM * VPW;           // 2 x [64][68]
    float* Kb  = Qb + 2 * BM * QP;         // 2 x [64][68]
    float* PB  = Kb + 2 * BM * QP;         // [64][68]
    float* SB  = PB + BM * PP;             // 512 floats stats

    const int tid  = threadIdx.x;
    const int lane = tid & 31;
    const int warp = tid >> 5;
    const int g    = lane >> 2;            // 0..7
    const int tg   = lane & 3;             // 0..3
    const int wr   = warp & 3;             // row group (16 rows)
    const int wq   = warp >> 2;            // QK col group / PV d quarter
    const int rb   = wr * 16;

    const int bid = blockIdx.x;
    const int b   = bid & 7;
    const int qb  = (S_ / BM - 1) - (bid >> 3);   // heavy blocks in wave 1

    const float* Qg = Q + ((size_t)b * S_ + (size_t)qb * BM) * D_;
    const float* Kg = K + (size_t)b * S_ * D_;
    const float* Vg = V + (size_t)b * S_ * D_;
    float*       Og = Oout + ((size_t)b * S_ + (size_t)qb * BM) * D_;

    float m0 = -1e30f, m1 = -1e30f, l0 = 0.f, l1 = 0.f;
    const float scale = 0.0220970869120796f;  // 1/sqrt(2048)
    const int i0 = qb * BM + rb + g;
    const int i1 = i0 + 8;

    float o[16][4];
#pragma unroll
    for (int nt = 0; nt < 16; ++nt) {
        o[nt][0] = 0.f; o[nt][1] = 0.f; o[nt][2] = 0.f; o[nt][3] = 0.f;
    }

    for (int kvb = 0; kvb <= qb; ++kvb) {
        const float* Kgb = Kg + (size_t)kvb * BN * D_;
        const float* Vgb = Vg + (size_t)kvb * BN * D_;

        __syncthreads();   // prev iteration fully done with all buffers

        // ---- phase 1: S = Q K^T, pipelined over 8 d-chunks; V rides along ----
        cp64(Qb, QP, Qg, tid);
        cp64(Kb, QP, Kgb, tid);
        cp64(Vsm, VPW, Vgb, tid);
        CP_COMMIT();

        float c[2][4];
        c[0][0]=0.f;c[0][1]=0.f;c[0][2]=0.f;c[0][3]=0.f;
        c[1][0]=0.f;c[1][1]=0.f;c[1][2]=0.f;c[1][3]=0.f;

        const bool live = !(kvb == qb && wq > wr);

        for (int dc = 0; dc < NDC; ++dc) {
            CP_WAIT(0);
            __syncthreads();
            if (dc + 1 < NDC) {
                int nb = (dc + 1) & 1;
                cp64(Qb + nb * BM * QP, QP, Qg + (dc + 1) * DC, tid);
                cp64(Kb + nb * BM * QP, QP, Kgb + (dc + 1) * DC, tid);
                cp64(Vsm + (dc + 1) * DC, VPW, Vgb + (dc + 1) * DC, tid);
                CP_COMMIT();
            }
            if (live) {
                const float* Qs = Qb + (dc & 1) * BM * QP;
                const float* Ks = Kb + (dc & 1) * BM * QP;
#pragma unroll
                for (int kk = 0; kk < 8; ++kk) {
                    const float* qr = Qs + (rb + g) * QP + kk * 8 + tg;
                    uint32_t a0 = f2tf(qr[0]);
                    uint32_t a1 = f2tf(qr[8 * QP]);
                    uint32_t a2 = f2tf(qr[4]);
                    uint32_t a3 = f2tf(qr[8 * QP + 4]);
#pragma unroll
                    for (int nt = 0; nt < 2; ++nt) {
                        const float* kr = Ks + (wq * 16 + nt * 8 + g) * QP + kk * 8 + tg;
                        uint32_t b0 = f2tf(kr[0]);
                        uint32_t b1 = f2tf(kr[4]);
                        mma8(c[nt][0], c[nt][1], c[nt][2], c[nt][3], a0, a1, a2, a3, b0, b1);
                    }
                }
            }
        }

        // ---- phase 2: bias + mask + online softmax (4-way cross-warp stats) ----
        const int jb = kvb * BN + wq * 16;
        float mx0 = -1e30f, mx1 = -1e30f;
#pragma unroll
        for (int nt = 0; nt < 2; ++nt) {
#pragma unroll
            for (int kq = 0; kq < 4; ++kq) {
                int i = (kq < 2) ? i0 : i1;
                int j = jb + nt * 8 + 2 * tg + (kq & 1);
                float s;
                if (j > i) {
                    s = -1e30f;
                } else {
                    float d = (float)(i - j);
                    s = c[nt][kq] * scale + 1.f / (1.f + 0.2f * d * d);
                }
                c[nt][kq] = s;
                if (kq < 2) mx0 = fmaxf(mx0, s); else mx1 = fmaxf(mx1, s);
            }
        }
        mx0 = fmaxf(mx0, __shfl_xor_sync(0xffffffffu, mx0, 1));
        mx0 = fmaxf(mx0, __shfl_xor_sync(0xffffffffu, mx0, 2));
        mx1 = fmaxf(mx1, __shfl_xor_sync(0xffffffffu, mx1, 1));
        mx1 = fmaxf(mx1, __shfl_xor_sync(0xffffffffu, mx1, 2));
        if (tg == 0) {
            SB[wq * 64 + rb + g]     = mx0;
            SB[wq * 64 + rb + g + 8] = mx1;
        }
        __syncthreads();
#pragma unroll
        for (int q = 0; q < 4; ++q) {
            mx0 = fmaxf(mx0, SB[q * 64 + rb + g]);
            mx1 = fmaxf(mx1, SB[q * 64 + rb + g + 8]);
        }
        float mn0 = fmaxf(m0, mx0), mn1 = fmaxf(m1, mx1);
        float al0 = __expf(m0 - mn0), al1 = __expf(m1 - mn1);
        m0 = mn0; m1 = mn1;

        float su0 = 0.f, su1 = 0.f;
#pragma unroll
        for (int nt = 0; nt < 2; ++nt) {
            float p0 = __expf(c[nt][0] - mn0);
            float p1 = __expf(c[nt][1] - mn0);
            float p2 = __expf(c[nt][2] - mn1);
            float p3 = __expf(c[nt][3] - mn1);
            su0 += p0 + p1; su1 += p2 + p3;
            c[nt][0] = p0; c[nt][1] = p1; c[nt][2] = p2; c[nt][3] = p3;
        }
        su0 += __shfl_xor_sync(0xffffffffu, su0, 1);
        su0 += __shfl_xor_sync(0xffffffffu, su0, 2);
        su1 += __shfl_xor_sync(0xffffffffu, su1, 1);
        su1 += __shfl_xor_sync(0xffffffffu, su1, 2);
        if (tg == 0) {
            SB[256 + wq * 64 + rb + g]     = su0;
            SB[256 + wq * 64 + rb + g + 8] = su1;
        }
        // ---- phase 3: P -> smem (tf32-formatted) ----
#pragma unroll
        for (int nt = 0; nt < 2; ++nt) {
            float2 pa, pb2;
            pa.x  = __uint_as_float(f2tf(c[nt][0]));
            pa.y  = __uint_as_float(f2tf(c[nt][1]));
            pb2.x = __uint_as_float(f2tf(c[nt][2]));
            pb2.y = __uint_as_float(f2tf(c[nt][3]));
            int colb = wq * 16 + nt * 8 + 2 * tg;
            *reinterpret_cast<float2*>(PB + (rb + g) * PP + colb)     = pa;
            *reinterpret_cast<float2*>(PB + (rb + g + 8) * PP + colb) = pb2;
        }
        __syncthreads();   // P + sum partials visible to everyone

        float s0 = 0.f, s1 = 0.f;
#pragma unroll
        for (int q = 0; q < 4; ++q) {
            s0 += SB[256 + q * 64 + rb + g];
            s1 += SB[256 + q * 64 + rb + g + 8];
        }
        l0 = l0 * al0 + s0;
        l1 = l1 * al1 + s1;

        // ---- phase 4: O = O*alpha + P V (V already resident in smem) ----
#pragma unroll
        for (int nt = 0; nt < 16; ++nt) {
            o[nt][0] *= al0; o[nt][1] *= al0;
            o[nt][2] *= al1; o[nt][3] *= al1;
        }
#pragma unroll
        for (int kk = 0; kk < 8; ++kk) {
            const float* pr = PB + (rb + g) * PP + kk * 8 + tg;
            uint32_t a0 = __float_as_uint(pr[0]);
            uint32_t a1 = __float_as_uint(pr[8 * PP]);
            uint32_t a2 = __float_as_uint(pr[4]);
            uint32_t a3 = __float_as_uint(pr[8 * PP + 4]);
            const float* vbase = Vsm + (kk * 8 + tg) * VPW + wq * 128 + g;
#pragma unroll
            for (int nt = 0; nt < 16; ++nt) {
                uint32_t b0 = f2tf(vbase[nt * 8]);
                uint32_t b1 = f2tf(vbase[nt * 8 + 4 * VPW]);
                mma8(o[nt][0], o[nt][1], o[nt][2], o[nt][3], a0, a1, a2, a3, b0, b1);
            }
        }
    }

    // ---- epilogue: out = O / l (direct from registers) ----
    float inv0 = 1.0f / l0;
    float inv1 = 1.0f / l1;
#pragma unroll
    for (int nt = 0; nt < 16; ++nt) {
        int colb = wq * 128 + nt * 8 + 2 * tg;
        *reinterpret_cast<float2*>(Og + (size_t)(rb + g) * D_ + colb) =
            make_float2(o[nt][0] * inv0, o[nt][1] * inv0);
        *reinterpret_cast<float2*>(Og + (size_t)(rb + g + 8) * D_ + colb) =
            make_float2(o[nt][2] * inv1, o[nt][3] * inv1);
    }
}

extern "C" void kernel_launch(void* const* d_in, const int* in_sizes, int n_in,
                              void* d_out, int out_size) {
    (void)in_sizes; (void)n_in; (void)out_size;
    const float* Q = (const float*)d_in[0];
    const float* K = (const float*)d_in[1];
    const float* V = (const float*)d_in[2];
    float* O = (float*)d_out;

    const size_t smem = (size_t)(BM * VPW + 4 * BM * QP + BM * PP + 512) * sizeof(float); // 222208
    cudaFuncSetAttribute(attn_tf32_kernel,
                         cudaFuncAttributeMaxDynamicSharedMemorySize, (int)smem);

    attn_tf32_kernel<<<S_ / BM * B_, NT, smem>>>(Q, K, V, O);
}